// round 1
// baseline (speedup 1.0000x reference)
#include <cuda_runtime.h>
#include <cuda_bf16.h>

// SSIM loss, fused separable implementation.
// pred, target: (N=16, C=3, H=512, W=512) fp32.  Output: scalar fp32 = 1 - mean(ssim_map).
//
// One main kernel per 64x16 output tile per plane:
//   1. stage pred/target tile (+5 halo) into smem
//   2. horizontal 11-tap pass producing 5 fields (wp, wt, wpp, wtt, wpt) into smem
//      (register-blocked: 4 outputs/thread from float4 LDS)
//   3. vertical 11-tap pass (register-blocked: 4 output rows/thread, one column)
//   4. ssim map value per pixel, block reduction, double atomicAdd
// init kernel zeroes the accumulator; final kernel writes 1 - sum/count.

#define TW 64
#define TH 16
#define RAD 5
#define INW 74      // TW + 2*RAD
#define INWP 76     // padded to multiple of 4 floats (16B) for float4 LDS
#define INH 26      // TH + 2*RAD
#define HW 512
#define PLANE_ELEMS (512 * 512)

__device__ double g_ssim_accum;

__global__ void ssim_init_kernel() { g_ssim_accum = 0.0; }

__global__ void ssim_final_kernel(float* out, float inv_count) {
    out[0] = 1.0f - (float)(g_ssim_accum) * inv_count;
}

__global__ __launch_bounds__(256) void ssim_main_kernel(
    const float* __restrict__ pred,
    const float* __restrict__ target)
{
    __shared__ __align__(16) float sp[INH][INWP];
    __shared__ __align__(16) float st[INH][INWP];
    __shared__ __align__(16) float hb[5][INH][TW];
    __shared__ float red[8];

    const int tid = threadIdx.x;
    const int x0 = blockIdx.x * TW;
    const int y0 = blockIdx.y * TH;
    const size_t plane_off = (size_t)blockIdx.z * PLANE_ELEMS;
    const float* __restrict__ pp = pred + plane_off;
    const float* __restrict__ tt = target + plane_off;

    // Gaussian weights (sigma = 1.5, window 11), computed in registers.
    float w[11];
    {
        float s = 0.f;
#pragma unroll
        for (int i = 0; i < 11; i++) {
            float x = (float)(i - RAD);
            w[i] = expf(-x * x * (1.0f / 4.5f));
            s += w[i];
        }
        float inv = 1.0f / s;
#pragma unroll
        for (int i = 0; i < 11; i++) w[i] *= inv;
    }

    // ---- Phase 1: stage input tile (with zero padding outside image) ----
    for (int i = tid; i < INH * INWP; i += 256) {
        int ly = i / INWP;
        int lx = i - ly * INWP;
        int gy = y0 - RAD + ly;
        int gx = x0 - RAD + lx;
        float pv = 0.f, tv = 0.f;
        if (lx < INW && gx >= 0 && gx < HW && gy >= 0 && gy < HW) {
            int gi = gy * HW + gx;
            pv = __ldg(pp + gi);
            tv = __ldg(tt + gi);
        }
        sp[ly][lx] = pv;
        st[ly][lx] = tv;
    }
    __syncthreads();

    // ---- Phase 2: horizontal pass, 4 consecutive output cols per item ----
    // Items: INH rows x 16 col-groups = 416.
    for (int item = tid; item < INH * 16; item += 256) {
        int r = item >> 4;
        int c0 = (item & 15) << 2;

        float p[16], t[16];
#pragma unroll
        for (int q = 0; q < 4; q++) {
            float4 v = *(const float4*)&sp[r][c0 + 4 * q];
            p[4 * q + 0] = v.x; p[4 * q + 1] = v.y;
            p[4 * q + 2] = v.z; p[4 * q + 3] = v.w;
            float4 u = *(const float4*)&st[r][c0 + 4 * q];
            t[4 * q + 0] = u.x; t[4 * q + 1] = u.y;
            t[4 * q + 2] = u.z; t[4 * q + 3] = u.w;
        }

        float a0[4] = {0.f, 0.f, 0.f, 0.f};
        float a1[4] = {0.f, 0.f, 0.f, 0.f};
        float a2[4] = {0.f, 0.f, 0.f, 0.f};
        float a3[4] = {0.f, 0.f, 0.f, 0.f};
        float a4[4] = {0.f, 0.f, 0.f, 0.f};
#pragma unroll
        for (int k = 0; k < 11; k++) {
            float wk = w[k];
#pragma unroll
            for (int j = 0; j < 4; j++) {
                float pv = p[j + k];
                float tv = t[j + k];
                float wp = wk * pv;
                float wt = wk * tv;
                a0[j] += wp;
                a1[j] += wt;
                a2[j] += wp * pv;
                a3[j] += wt * tv;
                a4[j] += wp * tv;
            }
        }
        *(float4*)&hb[0][r][c0] = make_float4(a0[0], a0[1], a0[2], a0[3]);
        *(float4*)&hb[1][r][c0] = make_float4(a1[0], a1[1], a1[2], a1[3]);
        *(float4*)&hb[2][r][c0] = make_float4(a2[0], a2[1], a2[2], a2[3]);
        *(float4*)&hb[3][r][c0] = make_float4(a3[0], a3[1], a3[2], a3[3]);
        *(float4*)&hb[4][r][c0] = make_float4(a4[0], a4[1], a4[2], a4[3]);
    }
    __syncthreads();

    // ---- Phase 3: vertical pass + SSIM map. 4 output rows per thread, one col.
    const int c = tid & 63;
    const int r0 = (tid >> 6) << 2;   // 0, 4, 8, 12

    float m1[4] = {0.f, 0.f, 0.f, 0.f};
    float m2[4] = {0.f, 0.f, 0.f, 0.f};
    float e1[4] = {0.f, 0.f, 0.f, 0.f};
    float e2[4] = {0.f, 0.f, 0.f, 0.f};
    float e12[4] = {0.f, 0.f, 0.f, 0.f};

#pragma unroll
    for (int rr = 0; rr < 14; rr++) {
        float v0 = hb[0][r0 + rr][c];
        float v1 = hb[1][r0 + rr][c];
        float v2 = hb[2][r0 + rr][c];
        float v3 = hb[3][r0 + rr][c];
        float v4 = hb[4][r0 + rr][c];
#pragma unroll
        for (int j = 0; j < 4; j++) {
            int k = rr - j;
            if (k >= 0 && k <= 10) {
                float wk = w[k];
                m1[j] += wk * v0;
                m2[j] += wk * v1;
                e1[j] += wk * v2;
                e2[j] += wk * v3;
                e12[j] += wk * v4;
            }
        }
    }

    const float C1 = 0.0001f;   // (0.01 * 1.0)^2
    const float C2 = 0.0009f;   // (0.03 * 1.0)^2
    float local = 0.f;
#pragma unroll
    for (int j = 0; j < 4; j++) {
        float mu1 = m1[j], mu2 = m2[j];
        float mu1s = mu1 * mu1;
        float mu2s = mu2 * mu2;
        float m12 = mu1 * mu2;
        float s1 = e1[j] - mu1s;
        float s2 = e2[j] - mu2s;
        float s12 = e12[j] - m12;
        float num = (2.0f * m12 + C1) * (2.0f * s12 + C2);
        float den = (mu1s + mu2s + C1) * (s1 + s2 + C2);
        local += num / den;
    }

    // ---- Block reduction -> double atomic ----
#pragma unroll
    for (int off = 16; off > 0; off >>= 1)
        local += __shfl_down_sync(0xffffffffu, local, off);
    if ((tid & 31) == 0) red[tid >> 5] = local;
    __syncthreads();
    if (tid < 8) {
        float v = red[tid];
#pragma unroll
        for (int off = 4; off > 0; off >>= 1)
            v += __shfl_down_sync(0x000000ffu, v, off);
        if (tid == 0) atomicAdd(&g_ssim_accum, (double)v);
    }
}

extern "C" void kernel_launch(void* const* d_in, const int* in_sizes, int n_in,
                              void* d_out, int out_size) {
    const float* pred = (const float*)d_in[0];
    const float* target = (const float*)d_in[1];
    float* out = (float*)d_out;

    const int total = in_sizes[0];                 // N*C*H*W
    const int nplanes = total / PLANE_ELEMS;       // N*C = 48

    ssim_init_kernel<<<1, 1>>>();
    dim3 grid(HW / TW, HW / TH, nplanes);          // (8, 32, 48)
    ssim_main_kernel<<<grid, 256>>>(pred, target);
    ssim_final_kernel<<<1, 1>>>(out, 1.0f / (float)total);
}

// round 2
// speedup vs baseline: 1.0658x; 1.0658x over previous
#include <cuda_runtime.h>
#include <cuda_bf16.h>

// SSIM loss, fused separable implementation, round 2.
// Key changes vs round 1:
//  - Gaussian weights hardcoded as compile-time literals -> FFMA-imm (rt 1 vs 2)
//  - horizontal pass restructured: products once per input point, 5 FFMA-imm/tap
//  - per-block partial sums to a device array (no init kernel, no global atomics)
//  - __fdividef for the SSIM map divide

#define TW 64
#define TH 16
#define RAD 5
#define INW 74      // TW + 2*RAD
#define INWP 76     // padded to 16B multiple for float4 LDS
#define INH 26      // TH + 2*RAD
#define HW 512
#define PLANE_ELEMS (512 * 512)
#define MAXBLOCKS 16384

// Gaussian(sigma=1.5, window=11), normalized; computed in fp64, rounded to fp32.
#define W0 0.00102838f
#define W1 0.00759877f
#define W2 0.03600077f
#define W3 0.10936070f
#define W4 0.21300554f
#define W5 0.26601173f

__device__ float g_partials[MAXBLOCKS];

__constant__ float c_dummy; // keep nvcc happy about empty constant use

__global__ void ssim_final_kernel(float* out, int nblocks, float inv_count) {
    __shared__ double sred[8];
    int tid = threadIdx.x;
    double acc = 0.0;
    for (int i = tid; i < nblocks; i += 256)
        acc += (double)g_partials[i];
#pragma unroll
    for (int off = 16; off > 0; off >>= 1)
        acc += __shfl_down_sync(0xffffffffu, acc, off);
    if ((tid & 31) == 0) sred[tid >> 5] = acc;
    __syncthreads();
    if (tid < 8) {
        double v = sred[tid];
#pragma unroll
        for (int off = 4; off > 0; off >>= 1)
            v += __shfl_down_sync(0x000000ffu, v, off);
        if (tid == 0) out[0] = 1.0f - (float)(v * (double)inv_count);
    }
}

__global__ __launch_bounds__(256) void ssim_main_kernel(
    const float* __restrict__ pred,
    const float* __restrict__ target)
{
    // weights as a constexpr array: with full unroll every W[k] becomes an
    // instruction immediate (FFMA-imm, rt_SMSP=1).
    constexpr float W[11] = {W0, W1, W2, W3, W4, W5, W4, W3, W2, W1, W0};

    __shared__ __align__(16) float sp[INH][INWP];
    __shared__ __align__(16) float st[INH][INWP];
    __shared__ __align__(16) float hb[5][INH][TW];
    __shared__ float red[8];

    const int tid = threadIdx.x;
    const int x0 = blockIdx.x * TW;
    const int y0 = blockIdx.y * TH;
    const size_t plane_off = (size_t)blockIdx.z * PLANE_ELEMS;
    const float* __restrict__ pp = pred + plane_off;
    const float* __restrict__ tt = target + plane_off;

    // ---- Phase 1: stage input tile (zero padding outside image) ----
    for (int i = tid; i < INH * INWP; i += 256) {
        int ly = i / INWP;
        int lx = i - ly * INWP;
        int gy = y0 - RAD + ly;
        int gx = x0 - RAD + lx;
        float pv = 0.f, tv = 0.f;
        if (lx < INW && gx >= 0 && gx < HW && gy >= 0 && gy < HW) {
            int gi = gy * HW + gx;
            pv = __ldg(pp + gi);
            tv = __ldg(tt + gi);
        }
        sp[ly][lx] = pv;
        st[ly][lx] = tv;
    }
    __syncthreads();

    // ---- Phase 2: horizontal 11-tap pass, 4 outputs per item ----
    // Loop over input points: 3 FMUL per point + 5 FFMA-imm per valid (tap,out).
    for (int item = tid; item < INH * 16; item += 256) {
        int r = item >> 4;
        int c0 = (item & 15) << 2;

        float p[16], t[16];
#pragma unroll
        for (int q = 0; q < 4; q++) {
            float4 v = *(const float4*)&sp[r][c0 + 4 * q];
            p[4 * q + 0] = v.x; p[4 * q + 1] = v.y;
            p[4 * q + 2] = v.z; p[4 * q + 3] = v.w;
            float4 u = *(const float4*)&st[r][c0 + 4 * q];
            t[4 * q + 0] = u.x; t[4 * q + 1] = u.y;
            t[4 * q + 2] = u.z; t[4 * q + 3] = u.w;
        }

        float a0[4] = {0.f, 0.f, 0.f, 0.f};
        float a1[4] = {0.f, 0.f, 0.f, 0.f};
        float a2[4] = {0.f, 0.f, 0.f, 0.f};
        float a3[4] = {0.f, 0.f, 0.f, 0.f};
        float a4[4] = {0.f, 0.f, 0.f, 0.f};
#pragma unroll
        for (int i = 0; i < 14; i++) {
            float pv = p[i];
            float tv = t[i];
            float qpp = pv * pv;
            float qtt = tv * tv;
            float qpt = pv * tv;
#pragma unroll
            for (int j = 0; j < 4; j++) {
                int k = i - j;
                if (k >= 0 && k <= 10) {
                    a0[j] += W[k] * pv;
                    a1[j] += W[k] * tv;
                    a2[j] += W[k] * qpp;
                    a3[j] += W[k] * qtt;
                    a4[j] += W[k] * qpt;
                }
            }
        }
        *(float4*)&hb[0][r][c0] = make_float4(a0[0], a0[1], a0[2], a0[3]);
        *(float4*)&hb[1][r][c0] = make_float4(a1[0], a1[1], a1[2], a1[3]);
        *(float4*)&hb[2][r][c0] = make_float4(a2[0], a2[1], a2[2], a2[3]);
        *(float4*)&hb[3][r][c0] = make_float4(a3[0], a3[1], a3[2], a3[3]);
        *(float4*)&hb[4][r][c0] = make_float4(a4[0], a4[1], a4[2], a4[3]);
    }
    __syncthreads();

    // ---- Phase 3: vertical pass + SSIM map. 4 output rows/thread, one column.
    const int c = tid & 63;
    const int r0 = (tid >> 6) << 2;   // 0, 4, 8, 12

    float m1[4]  = {0.f, 0.f, 0.f, 0.f};
    float m2[4]  = {0.f, 0.f, 0.f, 0.f};
    float e1[4]  = {0.f, 0.f, 0.f, 0.f};
    float e2[4]  = {0.f, 0.f, 0.f, 0.f};
    float e12[4] = {0.f, 0.f, 0.f, 0.f};

#pragma unroll
    for (int rr = 0; rr < 14; rr++) {
        float v0 = hb[0][r0 + rr][c];
        float v1 = hb[1][r0 + rr][c];
        float v2 = hb[2][r0 + rr][c];
        float v3 = hb[3][r0 + rr][c];
        float v4 = hb[4][r0 + rr][c];
#pragma unroll
        for (int j = 0; j < 4; j++) {
            int k = rr - j;
            if (k >= 0 && k <= 10) {
                m1[j]  += W[k] * v0;
                m2[j]  += W[k] * v1;
                e1[j]  += W[k] * v2;
                e2[j]  += W[k] * v3;
                e12[j] += W[k] * v4;
            }
        }
    }

    const float C1 = 0.0001f;   // (0.01)^2
    const float C2 = 0.0009f;   // (0.03)^2
    float local = 0.f;
#pragma unroll
    for (int j = 0; j < 4; j++) {
        float mu1 = m1[j], mu2 = m2[j];
        float mu1s = mu1 * mu1;
        float mu2s = mu2 * mu2;
        float m12 = mu1 * mu2;
        float s1 = e1[j] - mu1s;
        float s2 = e2[j] - mu2s;
        float s12 = e12[j] - m12;
        float num = (2.0f * m12 + C1) * (2.0f * s12 + C2);
        float den = (mu1s + mu2s + C1) * (s1 + s2 + C2);
        local += __fdividef(num, den);
    }

    // ---- Block reduction -> per-block partial (no atomics, no init) ----
#pragma unroll
    for (int off = 16; off > 0; off >>= 1)
        local += __shfl_down_sync(0xffffffffu, local, off);
    if ((tid & 31) == 0) red[tid >> 5] = local;
    __syncthreads();
    if (tid < 8) {
        float v = red[tid];
#pragma unroll
        for (int off = 4; off > 0; off >>= 1)
            v += __shfl_down_sync(0x000000ffu, v, off);
        if (tid == 0) {
            int bid = (blockIdx.z * gridDim.y + blockIdx.y) * gridDim.x + blockIdx.x;
            g_partials[bid] = v;
        }
    }
}

extern "C" void kernel_launch(void* const* d_in, const int* in_sizes, int n_in,
                              void* d_out, int out_size) {
    const float* pred = (const float*)d_in[0];
    const float* target = (const float*)d_in[1];
    float* out = (float*)d_out;

    const int total = in_sizes[0];                 // N*C*H*W
    const int nplanes = total / PLANE_ELEMS;       // N*C = 48

    dim3 grid(HW / TW, HW / TH, nplanes);          // (8, 32, 48) = 12288 blocks
    ssim_main_kernel<<<grid, 256>>>(pred, target);
    int nblocks = grid.x * grid.y * grid.z;
    ssim_final_kernel<<<1, 256>>>(out, nblocks, 1.0f / (float)total);
}

// round 3
// speedup vs baseline: 1.5507x; 1.4549x over previous
#include <cuda_runtime.h>
#include <cuda_bf16.h>

// SSIM loss, round 3: vertical-first separable conv, 4 fields, no raw staging.
//   Phase V: read raw pred/target directly from global (L1-cached, coalesced),
//            vertical 11-tap conv of {p, t, (p+t)^2, (p-t)^2} -> smem hb
//   Phase H: horizontal 11-tap conv (float4 register-blocked) + SSIM map
//   Per-block partial -> device array; tiny final kernel reduces.

#define TW 64
#define TH 16
#define RAD 5
#define INW 74      // TW + 2*RAD columns needed by horizontal pass
#define HBW 80      // padded row stride (16B multiple)
#define HW 512
#define PLANE_ELEMS (512 * 512)
#define NBLOCKS 12288

// Gaussian(sigma=1.5, window=11), normalized.
#define W0 0.00102838f
#define W1 0.00759877f
#define W2 0.03600077f
#define W3 0.10936070f
#define W4 0.21300554f
#define W5 0.26601173f

__device__ float g_partials[NBLOCKS];

__global__ __launch_bounds__(1024) void ssim_final_kernel(float* out, float inv_count) {
    __shared__ double sred[32];
    int tid = threadIdx.x;
    double acc = 0.0;
#pragma unroll
    for (int i = 0; i < NBLOCKS / 1024; i++)
        acc += (double)g_partials[i * 1024 + tid];
#pragma unroll
    for (int off = 16; off > 0; off >>= 1)
        acc += __shfl_down_sync(0xffffffffu, acc, off);
    if ((tid & 31) == 0) sred[tid >> 5] = acc;
    __syncthreads();
    if (tid < 32) {
        double v = sred[tid];
#pragma unroll
        for (int off = 16; off > 0; off >>= 1)
            v += __shfl_down_sync(0xffffffffu, v, off);
        if (tid == 0) out[0] = 1.0f - (float)(v * (double)inv_count);
    }
}

__global__ __launch_bounds__(256) void ssim_main_kernel(
    const float* __restrict__ pred,
    const float* __restrict__ target)
{
    constexpr float W[11] = {W0, W1, W2, W3, W4, W5, W4, W3, W2, W1, W0};

    // hb[field][row][col]: vertical-filtered fields. 4*16*80*4B = 20480B.
    __shared__ __align__(16) float hb[4][TH][HBW];
    __shared__ float red[8];

    const int tid = threadIdx.x;
    const int x0 = blockIdx.x * TW;
    const int y0 = blockIdx.y * TH;
    const size_t plane_off = (size_t)blockIdx.z * PLANE_ELEMS;
    const float* __restrict__ pp = pred + plane_off;
    const float* __restrict__ tt = target + plane_off;

    // ---- Phase V: vertical conv. Item = (column c in 0..73, row-group g in 0..3).
    // Thread computes 4 consecutive output rows of one column, reading 14 raw rows.
    for (int item = tid; item < INW * 4; item += 256) {
        int g = item / INW;          // row group
        int c = item - g * INW;      // column (consecutive across warp -> coalesced)
        int gx = x0 - RAD + c;
        bool xok = (gx >= 0) && (gx < HW);

        float a0[4] = {0.f, 0.f, 0.f, 0.f};   // conv p
        float a1[4] = {0.f, 0.f, 0.f, 0.f};   // conv t
        float a2[4] = {0.f, 0.f, 0.f, 0.f};   // conv (p+t)^2
        float a3[4] = {0.f, 0.f, 0.f, 0.f};   // conv (p-t)^2

#pragma unroll
        for (int rr = 0; rr < 14; rr++) {
            int gy = y0 - RAD + 4 * g + rr;
            float p = 0.f, t = 0.f;
            if (xok && gy >= 0 && gy < HW) {
                int gi = gy * HW + gx;
                p = __ldg(pp + gi);
                t = __ldg(tt + gi);
            }
            float s = p + t;
            float d = p - t;
            float ss = s * s;
            float dd = d * d;
#pragma unroll
            for (int j = 0; j < 4; j++) {
                int k = rr - j;
                if (k >= 0 && k <= 10) {
                    a0[j] += W[k] * p;
                    a1[j] += W[k] * t;
                    a2[j] += W[k] * ss;
                    a3[j] += W[k] * dd;
                }
            }
        }
#pragma unroll
        for (int j = 0; j < 4; j++) {
            hb[0][4 * g + j][c] = a0[j];
            hb[1][4 * g + j][c] = a1[j];
            hb[2][4 * g + j][c] = a2[j];
            hb[3][4 * g + j][c] = a3[j];
        }
    }
    __syncthreads();

    // ---- Phase H: horizontal conv + SSIM. Thread = 4 consecutive x, 1 row.
    // 16 x-groups * 16 rows = 256 items, perfectly balanced.
    const int r = tid >> 4;
    const int cg = (tid & 15) << 2;   // hb column base = output x base

    float v0[16], v1[16], v2[16], v3[16];
#pragma unroll
    for (int q = 0; q < 4; q++) {
        float4 u;
        u = *(const float4*)&hb[0][r][cg + 4 * q];
        v0[4*q] = u.x; v0[4*q+1] = u.y; v0[4*q+2] = u.z; v0[4*q+3] = u.w;
        u = *(const float4*)&hb[1][r][cg + 4 * q];
        v1[4*q] = u.x; v1[4*q+1] = u.y; v1[4*q+2] = u.z; v1[4*q+3] = u.w;
        u = *(const float4*)&hb[2][r][cg + 4 * q];
        v2[4*q] = u.x; v2[4*q+1] = u.y; v2[4*q+2] = u.z; v2[4*q+3] = u.w;
        u = *(const float4*)&hb[3][r][cg + 4 * q];
        v3[4*q] = u.x; v3[4*q+1] = u.y; v3[4*q+2] = u.z; v3[4*q+3] = u.w;
    }

    float m1[4]  = {0.f, 0.f, 0.f, 0.f};
    float m2[4]  = {0.f, 0.f, 0.f, 0.f};
    float cs[4]  = {0.f, 0.f, 0.f, 0.f};
    float cd[4]  = {0.f, 0.f, 0.f, 0.f};
#pragma unroll
    for (int i = 0; i < 14; i++) {
#pragma unroll
        for (int j = 0; j < 4; j++) {
            int k = i - j;
            if (k >= 0 && k <= 10) {
                m1[j] += W[k] * v0[i];
                m2[j] += W[k] * v1[i];
                cs[j] += W[k] * v2[i];
                cd[j] += W[k] * v3[i];
            }
        }
    }

    const float C1 = 0.0001f;   // (0.01)^2
    const float C2 = 0.0009f;   // (0.03)^2
    float local = 0.f;
#pragma unroll
    for (int j = 0; j < 4; j++) {
        float mu1 = m1[j], mu2 = m2[j];
        float mu1s = mu1 * mu1;
        float mu2s = mu2 * mu2;
        float m12  = mu1 * mu2;
        // E[pt] = (css - cdd)/4 ; E[pp]+E[tt] = (css + cdd)/2
        float ept   = 0.25f * (cs[j] - cd[j]);
        float epptt = 0.5f  * (cs[j] + cd[j]);
        float s12   = ept - m12;
        float ssum  = epptt - mu1s - mu2s;        // sigma1_sq + sigma2_sq
        float num = (2.0f * m12 + C1) * (2.0f * s12 + C2);
        float den = (mu1s + mu2s + C1) * (ssum + C2);
        local += __fdividef(num, den);
    }

    // ---- Block reduction -> per-block partial ----
#pragma unroll
    for (int off = 16; off > 0; off >>= 1)
        local += __shfl_down_sync(0xffffffffu, local, off);
    if ((tid & 31) == 0) red[tid >> 5] = local;
    __syncthreads();
    if (tid < 8) {
        float v = red[tid];
#pragma unroll
        for (int off = 4; off > 0; off >>= 1)
            v += __shfl_down_sync(0x000000ffu, v, off);
        if (tid == 0) {
            int bid = (blockIdx.z * gridDim.y + blockIdx.y) * gridDim.x + blockIdx.x;
            g_partials[bid] = v;
        }
    }
}

extern "C" void kernel_launch(void* const* d_in, const int* in_sizes, int n_in,
                              void* d_out, int out_size) {
    const float* pred = (const float*)d_in[0];
    const float* target = (const float*)d_in[1];
    float* out = (float*)d_out;

    const int total = in_sizes[0];                 // N*C*H*W
    const int nplanes = total / PLANE_ELEMS;       // 48

    dim3 grid(HW / TW, HW / TH, nplanes);          // (8, 32, 48) = 12288 blocks
    ssim_main_kernel<<<grid, 256>>>(pred, target);
    ssim_final_kernel<<<1, 1024>>>(out, 1.0f / (float)total);
}

// round 4
// speedup vs baseline: 1.6239x; 1.0472x over previous
#include <cuda_runtime.h>
#include <cuda_bf16.h>

// SSIM loss, round 4:
//  - single kernel: last block performs the global reduction (no final launch)
//  - phase H split into two field-pair batches (live regs 64 -> 32)
//  - __launch_bounds__(256, 4) to guarantee 4 blocks/SM
//  - interior/boundary template split for phase V (no predicates on fast path)

#define TW 64
#define TH 16
#define RAD 5
#define INW 74      // TW + 2*RAD columns needed by horizontal pass
#define HBW 80      // padded row stride (16B multiple)
#define HW 512
#define PLANE_ELEMS (512 * 512)
#define NBLOCKS 12288

// Gaussian(sigma=1.5, window=11), normalized.
#define W0 0.00102838f
#define W1 0.00759877f
#define W2 0.03600077f
#define W3 0.10936070f
#define W4 0.21300554f
#define W5 0.26601173f

__device__ float g_partials[NBLOCKS];
__device__ unsigned int g_counter = 0;

template<bool INTERIOR>
__device__ __forceinline__ void ssim_phase_v(
    const float* __restrict__ pp, const float* __restrict__ tt,
    int x0, int y0, int tid, float (*hb)[TH][HBW])
{
    constexpr float W[11] = {W0, W1, W2, W3, W4, W5, W4, W3, W2, W1, W0};
    for (int item = tid; item < INW * 4; item += 256) {
        int g = item / INW;          // row group (4 output rows each)
        int c = item - g * INW;      // column
        int gx = x0 - RAD + c;
        bool xok = INTERIOR || ((gx >= 0) && (gx < HW));

        float a0[4] = {0.f, 0.f, 0.f, 0.f};   // conv p
        float a1[4] = {0.f, 0.f, 0.f, 0.f};   // conv t
        float a2[4] = {0.f, 0.f, 0.f, 0.f};   // conv (p+t)^2
        float a3[4] = {0.f, 0.f, 0.f, 0.f};   // conv (p-t)^2

#pragma unroll
        for (int rr = 0; rr < 14; rr++) {
            int gy = y0 - RAD + 4 * g + rr;
            float p, t;
            if (INTERIOR) {
                int gi = gy * HW + gx;
                p = __ldg(pp + gi);
                t = __ldg(tt + gi);
            } else {
                p = 0.f; t = 0.f;
                if (xok && gy >= 0 && gy < HW) {
                    int gi = gy * HW + gx;
                    p = __ldg(pp + gi);
                    t = __ldg(tt + gi);
                }
            }
            float s = p + t;
            float d = p - t;
            float ss = s * s;
            float dd = d * d;
#pragma unroll
            for (int j = 0; j < 4; j++) {
                int k = rr - j;
                if (k >= 0 && k <= 10) {
                    a0[j] += W[k] * p;
                    a1[j] += W[k] * t;
                    a2[j] += W[k] * ss;
                    a3[j] += W[k] * dd;
                }
            }
        }
#pragma unroll
        for (int j = 0; j < 4; j++) {
            hb[0][4 * g + j][c] = a0[j];
            hb[1][4 * g + j][c] = a1[j];
            hb[2][4 * g + j][c] = a2[j];
            hb[3][4 * g + j][c] = a3[j];
        }
    }
}

__global__ __launch_bounds__(256, 4) void ssim_main_kernel(
    const float* __restrict__ pred,
    const float* __restrict__ target,
    float* __restrict__ out,
    float inv_count)
{
    constexpr float W[11] = {W0, W1, W2, W3, W4, W5, W4, W3, W2, W1, W0};

    __shared__ __align__(16) float hb[4][TH][HBW];   // 20480 B
    __shared__ float red[8];
    __shared__ bool s_last;

    const int tid = threadIdx.x;
    const int x0 = blockIdx.x * TW;
    const int y0 = blockIdx.y * TH;
    const size_t plane_off = (size_t)blockIdx.z * PLANE_ELEMS;
    const float* __restrict__ pp = pred + plane_off;
    const float* __restrict__ tt = target + plane_off;

    // ---- Phase V: vertical 11-tap conv of 4 fields into smem ----
    const bool interior =
        (x0 >= RAD) && (x0 + TW + RAD <= HW) && (y0 >= RAD) && (y0 + TH + RAD <= HW);
    if (interior) ssim_phase_v<true >(pp, tt, x0, y0, tid, hb);
    else          ssim_phase_v<false>(pp, tt, x0, y0, tid, hb);
    __syncthreads();

    // ---- Phase H: horizontal conv + SSIM map, two field-pair batches ----
    const int r = tid >> 4;
    const int cg = (tid & 15) << 2;   // output x base within tile

    float m1[4]  = {0.f, 0.f, 0.f, 0.f};
    float m2[4]  = {0.f, 0.f, 0.f, 0.f};
    {
        float v0[16], v1[16];
#pragma unroll
        for (int q = 0; q < 4; q++) {
            float4 u;
            u = *(const float4*)&hb[0][r][cg + 4 * q];
            v0[4*q] = u.x; v0[4*q+1] = u.y; v0[4*q+2] = u.z; v0[4*q+3] = u.w;
            u = *(const float4*)&hb[1][r][cg + 4 * q];
            v1[4*q] = u.x; v1[4*q+1] = u.y; v1[4*q+2] = u.z; v1[4*q+3] = u.w;
        }
#pragma unroll
        for (int i = 0; i < 14; i++) {
#pragma unroll
            for (int j = 0; j < 4; j++) {
                int k = i - j;
                if (k >= 0 && k <= 10) {
                    m1[j] += W[k] * v0[i];
                    m2[j] += W[k] * v1[i];
                }
            }
        }
    }
    float cs[4]  = {0.f, 0.f, 0.f, 0.f};
    float cd[4]  = {0.f, 0.f, 0.f, 0.f};
    {
        float v2[16], v3[16];
#pragma unroll
        for (int q = 0; q < 4; q++) {
            float4 u;
            u = *(const float4*)&hb[2][r][cg + 4 * q];
            v2[4*q] = u.x; v2[4*q+1] = u.y; v2[4*q+2] = u.z; v2[4*q+3] = u.w;
            u = *(const float4*)&hb[3][r][cg + 4 * q];
            v3[4*q] = u.x; v3[4*q+1] = u.y; v3[4*q+2] = u.z; v3[4*q+3] = u.w;
        }
#pragma unroll
        for (int i = 0; i < 14; i++) {
#pragma unroll
            for (int j = 0; j < 4; j++) {
                int k = i - j;
                if (k >= 0 && k <= 10) {
                    cs[j] += W[k] * v2[i];
                    cd[j] += W[k] * v3[i];
                }
            }
        }
    }

    const float C1 = 0.0001f;   // (0.01)^2
    const float C2 = 0.0009f;   // (0.03)^2
    float local = 0.f;
#pragma unroll
    for (int j = 0; j < 4; j++) {
        float mu1 = m1[j], mu2 = m2[j];
        float mu1s = mu1 * mu1;
        float mu2s = mu2 * mu2;
        float m12  = mu1 * mu2;
        float ept   = 0.25f * (cs[j] - cd[j]);     // E[pt]
        float epptt = 0.5f  * (cs[j] + cd[j]);     // E[pp] + E[tt]
        float s12   = ept - m12;
        float ssum  = epptt - mu1s - mu2s;         // sigma1_sq + sigma2_sq
        float num = (2.0f * m12 + C1) * (2.0f * s12 + C2);
        float den = (mu1s + mu2s + C1) * (ssum + C2);
        local += __fdividef(num, den);
    }

    // ---- Block reduction -> partial; last block reduces globally ----
#pragma unroll
    for (int off = 16; off > 0; off >>= 1)
        local += __shfl_down_sync(0xffffffffu, local, off);
    if ((tid & 31) == 0) red[tid >> 5] = local;
    __syncthreads();
    if (tid == 0) {
        float v = red[0] + red[1] + red[2] + red[3]
                + red[4] + red[5] + red[6] + red[7];
        int bid = (blockIdx.z * gridDim.y + blockIdx.y) * gridDim.x + blockIdx.x;
        g_partials[bid] = v;
        __threadfence();
        unsigned int n = atomicAdd(&g_counter, 1u);
        s_last = (n == NBLOCKS - 1u);
    }
    __syncthreads();

    if (s_last) {
        __threadfence();
        __shared__ double dred[8];
        const float4* __restrict__ p4 = (const float4*)g_partials;
        double acc = 0.0;
#pragma unroll
        for (int i = 0; i < NBLOCKS / 4 / 256; i++) {    // 12 iterations
            float4 v = p4[i * 256 + tid];
            acc += (double)v.x + (double)v.y + (double)v.z + (double)v.w;
        }
#pragma unroll
        for (int off = 16; off > 0; off >>= 1)
            acc += __shfl_down_sync(0xffffffffu, acc, off);
        if ((tid & 31) == 0) dred[tid >> 5] = acc;
        __syncthreads();
        if (tid == 0) {
            double s = dred[0] + dred[1] + dred[2] + dred[3]
                     + dred[4] + dred[5] + dred[6] + dred[7];
            out[0] = 1.0f - (float)(s * (double)inv_count);
            g_counter = 0;   // reset for next graph replay
        }
    }
}

extern "C" void kernel_launch(void* const* d_in, const int* in_sizes, int n_in,
                              void* d_out, int out_size) {
    const float* pred = (const float*)d_in[0];
    const float* target = (const float*)d_in[1];
    float* out = (float*)d_out;

    const int total = in_sizes[0];                 // N*C*H*W
    const int nplanes = total / PLANE_ELEMS;       // 48

    dim3 grid(HW / TW, HW / TH, nplanes);          // (8, 32, 48) = 12288 blocks
    ssim_main_kernel<<<grid, 256>>>(pred, target, out, 1.0f / (float)total);
}

// round 5
// speedup vs baseline: 2.0050x; 1.2347x over previous
#include <cuda_runtime.h>
#include <cuda_bf16.h>

// SSIM loss, round 5: 64x64 tiles, transposed-FIR vertical pass (16-row register
// blocking, 1.625 loads/output, products once per pixel), dynamic smem (80KB),
// 2 blocks/SM with 128-reg budget, single-batch H phase, fused final reduction.

#define TW 64
#define TH 64
#define RAD 5
#define INW 74         // TW + 2*RAD
#define HBW 80         // padded row stride (floats)
#define GROUPS 4       // row groups of 16
#define NITEMS (INW * GROUPS)   // 296
#define HW 512
#define PLANE_ELEMS (512 * 512)
#define NBLOCKS 3072

// Gaussian(sigma=1.5, window=11), normalized.
#define W0 0.00102838f
#define W1 0.00759877f
#define W2 0.03600077f
#define W3 0.10936070f
#define W4 0.21300554f
#define W5 0.26601173f

__device__ float g_partials[NBLOCKS];
__device__ unsigned int g_counter = 0;

// Vertical 11-tap conv of {p, t, (p+t)^2, (p-t)^2} for one column, 16 output
// rows, using an 11-deep accumulator ring (transposed FIR). 26 loads/column.
template<bool INTERIOR>
__device__ __forceinline__ void ssim_phase_v(
    const float* __restrict__ pp, const float* __restrict__ tt,
    int x0, int y0, int tid, float (*hb)[TH][HBW])
{
    constexpr float W[11] = {W0, W1, W2, W3, W4, W5, W4, W3, W2, W1, W0};

    for (int item = tid; item < NITEMS; item += 256) {
        int g = item / INW;
        int c = item - g * INW;
        int gx = x0 - RAD + c;
        int gybase = y0 + 16 * g - RAD;
        bool xok = INTERIOR || ((gx >= 0) && (gx < HW));
        const float* __restrict__ prow = pp + (size_t)gybase * HW + gx;
        const float* __restrict__ trow = tt + (size_t)gybase * HW + gx;

        float a0[11], a1[11], a2[11], a3[11];
#pragma unroll
        for (int s = 0; s < 11; s++) { a0[s] = 0.f; a1[s] = 0.f; a2[s] = 0.f; a3[s] = 0.f; }

#pragma unroll
        for (int rr = 0; rr < 26; rr++) {
            float p, t;
            if (INTERIOR) {
                p = __ldg(prow + rr * HW);
                t = __ldg(trow + rr * HW);
            } else {
                int gy = gybase + rr;
                p = 0.f; t = 0.f;
                if (xok && gy >= 0 && gy < HW) {
                    p = __ldg(prow + rr * HW);
                    t = __ldg(trow + rr * HW);
                }
            }
            float sv = p + t;
            float dv = p - t;
            float ss = sv * sv;
            float dd = dv * dv;
#pragma unroll
            for (int j = 0; j < 16; j++) {
                int k = rr - j;
                if (k >= 0 && k <= 10) {
                    int slot = j % 11;
                    a0[slot] += W[k] * p;
                    a1[slot] += W[k] * t;
                    a2[slot] += W[k] * ss;
                    a3[slot] += W[k] * dd;
                }
            }
            if (rr >= 10) {
                int j = rr - 10;
                int slot = j % 11;
                int row = 16 * g + j;
                hb[0][row][c] = a0[slot];  a0[slot] = 0.f;
                hb[1][row][c] = a1[slot];  a1[slot] = 0.f;
                hb[2][row][c] = a2[slot];  a2[slot] = 0.f;
                hb[3][row][c] = a3[slot];  a3[slot] = 0.f;
            }
        }
    }
}

__global__ __launch_bounds__(256, 2) void ssim_main_kernel(
    const float* __restrict__ pred,
    const float* __restrict__ target,
    float* __restrict__ out,
    float inv_count)
{
    constexpr float W[11] = {W0, W1, W2, W3, W4, W5, W4, W3, W2, W1, W0};

    extern __shared__ __align__(16) float smem_raw[];
    float (*hb)[TH][HBW] = (float (*)[TH][HBW])smem_raw;   // [4][64][80] = 80KB
    __shared__ float red[8];
    __shared__ bool s_last;

    const int tid = threadIdx.x;
    const int x0 = blockIdx.x * TW;
    const int y0 = blockIdx.y * TH;
    const size_t plane_off = (size_t)blockIdx.z * PLANE_ELEMS;
    const float* __restrict__ pp = pred + plane_off;
    const float* __restrict__ tt = target + plane_off;

    // ---- Phase V ----
    const bool interior =
        (x0 >= RAD) && (x0 + TW + RAD <= HW) && (y0 >= RAD) && (y0 + TH + RAD <= HW);
    if (interior) ssim_phase_v<true >(pp, tt, x0, y0, tid, hb);
    else          ssim_phase_v<false>(pp, tt, x0, y0, tid, hb);
    __syncthreads();

    // ---- Phase H: 4 items/thread, each = 4 consecutive x in one row ----
    const float C1 = 0.0001f;   // (0.01)^2
    const float C2 = 0.0009f;   // (0.03)^2
    float local = 0.f;

#pragma unroll
    for (int it = 0; it < 4; it++) {
        int h = tid + 256 * it;
        int r = h >> 4;
        int cg = (h & 15) << 2;

        float v0[16], v1[16], v2[16], v3[16];
#pragma unroll
        for (int q = 0; q < 4; q++) {
            float4 u;
            u = *(const float4*)&hb[0][r][cg + 4 * q];
            v0[4*q] = u.x; v0[4*q+1] = u.y; v0[4*q+2] = u.z; v0[4*q+3] = u.w;
            u = *(const float4*)&hb[1][r][cg + 4 * q];
            v1[4*q] = u.x; v1[4*q+1] = u.y; v1[4*q+2] = u.z; v1[4*q+3] = u.w;
            u = *(const float4*)&hb[2][r][cg + 4 * q];
            v2[4*q] = u.x; v2[4*q+1] = u.y; v2[4*q+2] = u.z; v2[4*q+3] = u.w;
            u = *(const float4*)&hb[3][r][cg + 4 * q];
            v3[4*q] = u.x; v3[4*q+1] = u.y; v3[4*q+2] = u.z; v3[4*q+3] = u.w;
        }

        float m1[4] = {0.f, 0.f, 0.f, 0.f};
        float m2[4] = {0.f, 0.f, 0.f, 0.f};
        float cs[4] = {0.f, 0.f, 0.f, 0.f};
        float cd[4] = {0.f, 0.f, 0.f, 0.f};
#pragma unroll
        for (int i = 0; i < 14; i++) {
#pragma unroll
            for (int j = 0; j < 4; j++) {
                int k = i - j;
                if (k >= 0 && k <= 10) {
                    m1[j] += W[k] * v0[i];
                    m2[j] += W[k] * v1[i];
                    cs[j] += W[k] * v2[i];
                    cd[j] += W[k] * v3[i];
                }
            }
        }

#pragma unroll
        for (int j = 0; j < 4; j++) {
            float mu1 = m1[j], mu2 = m2[j];
            float mu1s = mu1 * mu1;
            float mu2s = mu2 * mu2;
            float m12  = mu1 * mu2;
            float ept   = 0.25f * (cs[j] - cd[j]);     // E[pt]
            float epptt = 0.5f  * (cs[j] + cd[j]);     // E[pp] + E[tt]
            float s12   = ept - m12;
            float ssum  = epptt - mu1s - mu2s;         // sigma1^2 + sigma2^2
            float num = (2.0f * m12 + C1) * (2.0f * s12 + C2);
            float den = (mu1s + mu2s + C1) * (ssum + C2);
            local += __fdividef(num, den);
        }
    }

    // ---- Block reduction -> partial; last block reduces globally ----
#pragma unroll
    for (int off = 16; off > 0; off >>= 1)
        local += __shfl_down_sync(0xffffffffu, local, off);
    if ((tid & 31) == 0) red[tid >> 5] = local;
    __syncthreads();
    if (tid == 0) {
        float v = red[0] + red[1] + red[2] + red[3]
                + red[4] + red[5] + red[6] + red[7];
        int bid = (blockIdx.z * gridDim.y + blockIdx.y) * gridDim.x + blockIdx.x;
        g_partials[bid] = v;
        __threadfence();
        unsigned int n = atomicAdd(&g_counter, 1u);
        s_last = (n == NBLOCKS - 1u);
    }
    __syncthreads();

    if (s_last) {
        __threadfence();
        __shared__ double dred[8];
        const float4* __restrict__ p4 = (const float4*)g_partials;
        double acc = 0.0;
#pragma unroll
        for (int i = 0; i < NBLOCKS / 4 / 256; i++) {    // 3 iterations
            float4 v = p4[i * 256 + tid];
            acc += (double)v.x + (double)v.y + (double)v.z + (double)v.w;
        }
#pragma unroll
        for (int off = 16; off > 0; off >>= 1)
            acc += __shfl_down_sync(0xffffffffu, acc, off);
        if ((tid & 31) == 0) dred[tid >> 5] = acc;
        __syncthreads();
        if (tid == 0) {
            double s = dred[0] + dred[1] + dred[2] + dred[3]
                     + dred[4] + dred[5] + dred[6] + dred[7];
            out[0] = 1.0f - (float)(s * (double)inv_count);
            g_counter = 0;   // reset for next graph replay
        }
    }
}

extern "C" void kernel_launch(void* const* d_in, const int* in_sizes, int n_in,
                              void* d_out, int out_size) {
    const float* pred = (const float*)d_in[0];
    const float* target = (const float*)d_in[1];
    float* out = (float*)d_out;

    const int total = in_sizes[0];                 // N*C*H*W
    const int nplanes = total / PLANE_ELEMS;       // 48

    const size_t smem = sizeof(float) * 4 * TH * HBW;   // 81920 B
    cudaFuncSetAttribute(ssim_main_kernel,
                         cudaFuncAttributeMaxDynamicSharedMemorySize, (int)smem);

    dim3 grid(HW / TW, HW / TH, nplanes);          // (8, 8, 48) = 3072 blocks
    ssim_main_kernel<<<grid, 256, smem>>>(pred, target, out, 1.0f / (float)total);
}